// round 10
// baseline (speedup 1.0000x reference)
#include <cuda_runtime.h>
#include <math.h>

// ---------------------------------------------------------------------------
// FourierBlock: rfft(L=4096) -> top-16 |X| per (b,c) -> mask -> irfft
// x: [B=64, L=4096, C=128] f32
//
//   k0: twiddle init
//   k1: transpose [B,L,C] -> scratch [B,C,L]   (float4 on scratch side)
//   k2: per-series kernel (1 CTA / series, 6 CTAs/SM):
//        packed real FFT (complex 2048, radix 8,8,8,4; 1st pass reads gmem)
//        pair-fused untangle -> |X|^2 bits in registers
//        1024-bin histogram top-16 (all-warp threshold scan, boundary refine)
//        pair-fused mask + inverse untangle, in place
//        inverse FFT (conj trick); FINAL PASS WRITES out[b][l][c] DIRECTLY
//        (scattered 4B stores; adjacent-channel CTAs merge sectors in L2)
//   (no bwd transpose kernel)
// ---------------------------------------------------------------------------

#define BATCH 64
#define LEN   4096
#define CH    128
#define NC    2048
#define NF    2049
#define TPB   256
#define NBINS 1024
#define CAP   1024

#define MAP(i) ((i) + ((i) >> 4))
#define BUFSZ  (MAP(2048) + 8)

__device__ __align__(16) float g_scratch[BATCH * CH * LEN];
__device__ float2 g_tw[NC];          // cis(-2*pi*k/2048)
__device__ float2 g_twh[NF];         // H[f] = cis(-pi*f/2048)

// ------------------------------ warp redux ---------------------------------
__device__ __forceinline__ unsigned redux_max_u32(unsigned v) {
    unsigned r;
    asm("redux.sync.max.u32 %0, %1, 0xffffffff;" : "=r"(r) : "r"(v));
    return r;
}
__device__ __forceinline__ unsigned redux_min_u32(unsigned v) {
    unsigned r;
    asm("redux.sync.min.u32 %0, %1, 0xffffffff;" : "=r"(r) : "r"(v));
    return r;
}

// ------------------------------ complex helpers ----------------------------
__device__ __forceinline__ float2 cmul(float2 a, float2 b) {
    return make_float2(fmaf(a.x, b.x, -a.y * b.y), fmaf(a.x, b.y, a.y * b.x));
}
__device__ __forceinline__ float2 cadd(float2 a, float2 b) {
    return make_float2(a.x + b.x, a.y + b.y);
}
__device__ __forceinline__ float2 csub(float2 a, float2 b) {
    return make_float2(a.x - b.x, a.y - b.y);
}

__device__ __forceinline__ void dft4(float2 v[4]) {
    float2 t0 = cadd(v[0], v[2]);
    float2 t1 = csub(v[0], v[2]);
    float2 t2 = cadd(v[1], v[3]);
    float2 t3 = csub(v[1], v[3]);
    v[0] = cadd(t0, t2);
    v[2] = csub(t0, t2);
    v[1] = make_float2(t1.x + t3.y, t1.y - t3.x);
    v[3] = make_float2(t1.x - t3.y, t1.y + t3.x);
}

__device__ __forceinline__ void dft8(float2 v[8]) {
    float2 e[4] = { v[0], v[2], v[4], v[6] };
    float2 o[4] = { v[1], v[3], v[5], v[7] };
    dft4(e);
    dft4(o);
    const float s = 0.70710678118654752f;
    o[1] = make_float2(s * (o[1].x + o[1].y), s * (o[1].y - o[1].x));
    o[2] = make_float2(o[2].y, -o[2].x);
    o[3] = make_float2(s * (o[3].y - o[3].x), -s * (o[3].x + o[3].y));
#pragma unroll
    for (int k = 0; k < 4; k++) {
        v[k]     = cadd(e[k], o[k]);
        v[k + 4] = csub(e[k], o[k]);
    }
}

// ------------------------------ Stockham passes ----------------------------
template <int NS>
__device__ __forceinline__ void pass8(const float2* __restrict__ src,
                                      float2* __restrict__ dst, int j) {
    float2 v[8];
#pragma unroll
    for (int r = 0; r < 8; r++) v[r] = src[MAP(j + r * 256)];
    if (NS > 1) {
        int k0 = (j & (NS - 1)) * (256 / NS);
#pragma unroll
        for (int r = 1; r < 8; r++) v[r] = cmul(v[r], __ldg(&g_tw[k0 * r]));
    }
    dft8(v);
    int idxD = ((j & ~(NS - 1)) << 3) + (j & (NS - 1));
#pragma unroll
    for (int r = 0; r < 8; r++) dst[MAP(idxD + r * NS)] = v[r];
}

__device__ __forceinline__ void pass8_gmem(const float2* __restrict__ gsrc,
                                           float2* __restrict__ dst, int j) {
    float2 v[8];
#pragma unroll
    for (int r = 0; r < 8; r++) v[r] = gsrc[j + r * 256];
    dft8(v);
    int idxD = j << 3;
#pragma unroll
    for (int r = 0; r < 8; r++) dst[MAP(idxD + r)] = v[r];
}

__device__ __forceinline__ void pass4_512(const float2* __restrict__ src,
                                          float2* __restrict__ dst, int jj) {
    float2 v[4];
#pragma unroll
    for (int r = 0; r < 4; r++) v[r] = src[MAP(jj + r * 512)];
#pragma unroll
    for (int r = 1; r < 4; r++) v[r] = cmul(v[r], __ldg(&g_tw[jj * r]));
    dft4(v);
#pragma unroll
    for (int r = 0; r < 4; r++) dst[MAP(jj + r * 512)] = v[r];
}

// final inverse pass: dft4 then scattered direct store to out[b][l][c].
// obase = out + b*LEN*CH + c ; time sample l lives at obase[l*CH].
__device__ __forceinline__ void pass4_512_direct(const float2* __restrict__ src,
                                                 float* __restrict__ obase, int jj) {
    float2 v[4];
#pragma unroll
    for (int r = 0; r < 4; r++) v[r] = src[MAP(jj + r * 512)];
#pragma unroll
    for (int r = 1; r < 4; r++) v[r] = cmul(v[r], __ldg(&g_tw[jj * r]));
    dft4(v);
    const float inv = 1.0f / 2048.0f;
#pragma unroll
    for (int r = 0; r < 4; r++) {
        int n = jj + r * 512;                       // packed complex index
        obase[(size_t)(2 * n) * CH]     = v[r].x * inv;
        obase[(size_t)(2 * n + 1) * CH] = -v[r].y * inv;   // conj trick
    }
}

// bin index for thread t, slot i
__device__ __forceinline__ int slot_bin(int t, int i) {
    return (i < 4) ? (t + (i << 8)) : ((i < 8) ? (2048 - (t + ((i - 4) << 8))) : 1024);
}

// ------------------------------ main kernel --------------------------------
__global__ void __launch_bounds__(TPB, 6) fourier_block_kernel(float* __restrict__ out) {
    __shared__ float2   bufA[BUFSZ];
    __shared__ float2   bufB[BUFSZ];
    __shared__ unsigned maskbits[65];      // bit f set => keep bin f
    __shared__ unsigned s_bcnt;

    // histogram + boundary candidates alias bufB (dead between FFTs)
    unsigned* hist  = reinterpret_cast<unsigned*>(bufB);
    unsigned* candV = hist + NBINS;
    unsigned* candB = candV + CAP;

    const int tid  = threadIdx.x;
    const int lane = tid & 31;
    const int w    = tid >> 5;
    const int ser  = blockIdx.x;                   // b*128 + c
    float2* series = reinterpret_cast<float2*>(g_scratch) + (size_t)ser * NC;
    float* obase   = out + (size_t)(ser >> 7) * LEN * CH + (ser & 127);

    // dedicated smem zeroing at entry (ordered before use by FFT syncs)
    if (tid < 65) maskbits[tid] = 0u;
    if (tid == 0) s_bcnt = 0u;

    // ---------------- forward FFT (gmem -> bufA) ----------------
    pass8_gmem(series, bufB, tid);
    __syncthreads();
    pass8<8>(bufB, bufA, tid);
    __syncthreads();
    pass8<64>(bufA, bufB, tid);
    __syncthreads();
    pass4_512(bufB, bufA, tid);
    pass4_512(bufB, bufA, tid + 256);
    __syncthreads();                                   // Z in bufA; bufB dead

    // zero hist (aliases bufB => only after the sync above)
#pragma unroll
    for (int q = 0; q < 4; q++) hist[tid + (q << 8)] = 0u;

    // ---------------- pairs pass 1: |X|^2 bits into registers ----------------
    unsigned fb[9];
#pragma unroll
    for (int q = 0; q < 4; q++) {
        int p = tid + (q << 8);                        // 0..1023
        float2 Zf = bufA[MAP(p)];
        float2 Zn = bufA[MAP((NC - p) & (NC - 1))];
        float2 S  = make_float2(Zf.x + Zn.x, Zf.y - Zn.y);
        float2 D  = make_float2(Zf.x - Zn.x, Zf.y + Zn.y);
        float2 H  = __ldg(&g_twh[p]);
        float2 T  = cmul(make_float2(-H.y, H.x), D);   // i*H*D
        float2 XA = make_float2(S.x - T.x, S.y - T.y); // 2*X[p]
        float2 XB = make_float2(S.x + T.x, S.y + T.y); // 2*conj(X[2048-p])
        fb[q]     = __float_as_uint(fmaf(XA.x, XA.x, XA.y * XA.y));
        fb[q + 4] = __float_as_uint(fmaf(XB.x, XB.x, XB.y * XB.y));
    }
    fb[8] = 0u;
    if (tid == 0) {                                    // bin 1024 (self-pair)
        float2 Zf = bufA[MAP(1024)];
        float2 S  = make_float2(2.0f * Zf.x, 0.0f);
        float2 D  = make_float2(0.0f, 2.0f * Zf.y);
        float2 H  = __ldg(&g_twh[1024]);
        float2 T  = cmul(make_float2(-H.y, H.x), D);
        float2 XA = make_float2(S.x - T.x, S.y - T.y);
        fb[8] = __float_as_uint(fmaf(XA.x, XA.x, XA.y * XA.y));
    }
    const int nv = (tid == 0) ? 9 : 8;
    __syncthreads();                                   // hist zero visible

    // ---------------- histogram of bit-prefixes ----------------
    for (int i = 0; i < nv; i++)
        atomicAdd(&hist[fb[i] >> 22], 1u);
    __syncthreads();

    // ------- threshold scan: every warp redundantly (no broadcast sync) -------
    unsigned T_, cgt;
    {
        int hi = (NBINS - 1) - lane * 32;              // lane0 covers top bins
        unsigned s = 0;
        for (int b2 = 0; b2 < 32; b2++) s += hist[hi - b2];
        unsigned cum = s;
#pragma unroll
        for (int o = 1; o < 32; o <<= 1) {
            unsigned t2 = __shfl_up_sync(0xffffffffu, cum, o);
            if (lane >= o) cum += t2;
        }
        unsigned excl = cum - s;                       // strictly-above count
        bool hit = (excl < 16u) && (excl + s >= 16u);
        unsigned hm = __ballot_sync(0xffffffffu, hit);
        int hl = __ffs(hm) - 1;
        unsigned tT = 0u, tc = 0u;
        if (lane == hl) {
            unsigned run = excl;
            int b = hi;
            while (run + hist[b] < 16u) { run += hist[b]; b--; }
            tT = (unsigned)b;
            tc = run;
        }
        T_  = __shfl_sync(0xffffffffu, tT, hl);
        cgt = __shfl_sync(0xffffffffu, tc, hl);
    }

    // ---------------- classify: definite keeps + boundary candidates ----------
    for (int i = 0; i < nv; i++) {
        unsigned pf = fb[i] >> 22;
        if (pf > T_) {
            int bn = slot_bin(tid, i);
            atomicOr(&maskbits[bn >> 5], 1u << (bn & 31));
        } else if (pf == T_) {
            unsigned s2 = atomicAdd(&s_bcnt, 1u);
            if (s2 < CAP) {
                candV[s2] = fb[i];
                candB[s2] = (unsigned)slot_bin(tid, i);
            }
        }
    }
    __syncthreads();

    // ---------------- warp0: pick remaining from boundary bin ----------------
    if (w == 0) {
        int need = 16 - (int)cgt;
        int m = (int)(s_bcnt < CAP ? s_bcnt : CAP);
        for (int it = 0; it < need; it++) {
            unsigned bv = 0u, bb = 0xFFFFFFFFu;
            for (int j = lane; j < m; j += 32) {
                unsigned v2 = candV[j], b2 = candB[j];
                if (v2 > bv || (v2 == bv && b2 < bb)) { bv = v2; bb = b2; }
            }
            unsigned best = redux_max_u32(bv);
            unsigned mb2 = (bv == best) ? bb : 0xFFFFFFFFu;
            unsigned wb = redux_min_u32(mb2);
            if (lane == 0) maskbits[wb >> 5] |= 1u << (wb & 31);
            for (int j = lane; j < m; j += 32)
                if (candB[j] == wb) candV[j] = 0u;
        }
    }
    __syncthreads();

    // ------- pairs pass 2: mask + inverse untangle, in place, no sync -------
#pragma unroll
    for (int q = 0; q < 5; q++) {
        int p = tid + (q << 8);
        if (q == 4 && tid != 0) break;
        if (q == 4) p = 1024;
        int binB = 2048 - p;
        unsigned ka = (maskbits[p >> 5] >> (p & 31)) & 1u;
        unsigned kb = (maskbits[binB >> 5] >> (binB & 31)) & 1u;
        if (!(ka | kb)) {                               // fast path: both dropped
            bufA[MAP(p)] = make_float2(0.0f, 0.0f);
            if (p != 0 && p != 1024)
                bufA[MAP(binB)] = make_float2(0.0f, 0.0f);
            continue;
        }
        int pm = (NC - p) & (NC - 1);
        float2 Zf = bufA[MAP(p)];
        float2 Zn = bufA[MAP(pm)];
        float2 S  = make_float2(Zf.x + Zn.x, Zf.y - Zn.y);
        float2 D  = make_float2(Zf.x - Zn.x, Zf.y + Zn.y);
        float2 H  = __ldg(&g_twh[p]);
        float2 T  = cmul(make_float2(-H.y, H.x), D);
        float2 A  = ka ? make_float2(0.5f * (S.x - T.x), 0.5f * (S.y - T.y))
                       : make_float2(0.0f, 0.0f);
        float2 Bc = kb ? make_float2(0.5f * (S.x + T.x), 0.5f * (S.y + T.y))
                       : make_float2(0.0f, 0.0f);       // conj(X'[2048-p])
        float2 St = make_float2(A.x + Bc.x, A.y + Bc.y);
        float2 Q  = make_float2(Bc.x - A.x, Bc.y - A.y);
        float2 Dt = cmul(make_float2(-H.y, -H.x), Q);   // -i*conj(H)*Q
        bufA[MAP(p)] = make_float2(0.5f * (St.x + Dt.x), -0.5f * (St.y + Dt.y));
        if (p != 0 && p != 1024)
            bufA[MAP(binB)] = make_float2(0.5f * (St.x - Dt.x), 0.5f * (St.y - Dt.y));
    }
    __syncthreads();

    // ---------------- inverse FFT via conj trick (bufA -> out direct) ----------
    pass8<1>(bufA, bufB, tid);
    __syncthreads();
    pass8<8>(bufB, bufA, tid);
    __syncthreads();
    pass8<64>(bufA, bufB, tid);
    __syncthreads();
    pass4_512_direct(bufB, obase, tid);
    pass4_512_direct(bufB, obase, tid + 256);
}

// ------------------------------ twiddle init -------------------------------
__global__ void twiddle_init_kernel() {
    int k = blockIdx.x * blockDim.x + threadIdx.x;
    const double PI = 3.14159265358979323846;
    if (k < NC) {
        double ang = -2.0 * PI * (double)k / (double)NC;
        g_tw[k] = make_float2((float)cos(ang), (float)sin(ang));
    }
    if (k < NF) {
        double th = PI * (double)k / (double)NC;
        g_twh[k] = make_float2((float)cos(th), (float)(-sin(th)));
    }
}

// ------------------------------ fwd transpose ------------------------------
// fwd: x[b][l][c] -> scratch[b][c][l]; scratch side uses float4.
__global__ void __launch_bounds__(256) transpose_fwd_kernel(const float* __restrict__ x) {
    __shared__ float tile[32][129];
    const int b  = blockIdx.z;
    const int c0 = blockIdx.x * 32;
    const int l0 = blockIdx.y * 128;
    const float* xb = x + (size_t)b * LEN * CH;
    float* sb = g_scratch + (size_t)b * CH * LEN;
    const int lane = threadIdx.x & 31;
    const int wrp  = threadIdx.x >> 5;     // 0..7
#pragma unroll
    for (int k = 0; k < 16; k++) {
        int l = wrp + k * 8;
        tile[lane][l] = xb[(size_t)(l0 + l) * CH + (c0 + lane)];
    }
    __syncthreads();
#pragma unroll
    for (int m = 0; m < 4; m++) {
        int c = wrp * 4 + m;
        float4 v = make_float4(tile[c][4 * lane + 0], tile[c][4 * lane + 1],
                               tile[c][4 * lane + 2], tile[c][4 * lane + 3]);
        *reinterpret_cast<float4*>(&sb[(size_t)(c0 + c) * LEN + l0 + 4 * lane]) = v;
    }
}

// ------------------------------ launch -------------------------------------
extern "C" void kernel_launch(void* const* d_in, const int* in_sizes, int n_in,
                              void* d_out, int out_size) {
    const float* x = (const float*)d_in[0];
    float* out = (float*)d_out;

    twiddle_init_kernel<<<9, 256>>>();
    transpose_fwd_kernel<<<dim3(CH / 32, LEN / 128, BATCH), 256>>>(x);
    fourier_block_kernel<<<BATCH * CH, TPB>>>(out);
}

// round 11
// speedup vs baseline: 1.3446x; 1.3446x over previous
#include <cuda_runtime.h>
#include <math.h>

// ---------------------------------------------------------------------------
// FourierBlock: rfft(L=4096) -> top-16 |X| per (b,c) -> mask -> irfft
// x: [B=64, L=4096, C=128] f32
//
//   k0: twiddle init (1 value/thread, sincospi, 65 blocks x 32 -> ~1us)
//   k1: transpose [B,L,C] -> scratch [B,C,L]   (float4 on scratch side)
//   k2: per-series kernel (1 CTA / series, 6 CTAs/SM):
//        packed real FFT (complex 2048, radix 8,8,8,4; 1st pass reads gmem)
//        pair-fused untangle -> |X|^2 bits in registers
//        1024-bin histogram top-16 (all-warp threshold scan, warp0 refine)
//        pair-fused mask + inverse untangle, in place
//        inverse FFT (conj trick; last pass writes scratch with scale+conj)
//   k3: transpose scratch [B,C,L] -> out [B,L,C]
// ---------------------------------------------------------------------------

#define BATCH 64
#define LEN   4096
#define CH    128
#define NC    2048
#define NF    2049
#define TPB   256
#define NBINS 1024
#define CAP   1024

#define MAP(i) ((i) + ((i) >> 4))
#define BUFSZ  (MAP(2048) + 8)

__device__ __align__(16) float g_scratch[BATCH * CH * LEN];
__device__ float2 g_tw[NC];          // cis(-2*pi*k/2048)
__device__ float2 g_twh[NF];         // H[f] = cis(-pi*f/2048)

// ------------------------------ warp redux ---------------------------------
__device__ __forceinline__ unsigned redux_max_u32(unsigned v) {
    unsigned r;
    asm("redux.sync.max.u32 %0, %1, 0xffffffff;" : "=r"(r) : "r"(v));
    return r;
}
__device__ __forceinline__ unsigned redux_min_u32(unsigned v) {
    unsigned r;
    asm("redux.sync.min.u32 %0, %1, 0xffffffff;" : "=r"(r) : "r"(v));
    return r;
}

// ------------------------------ complex helpers ----------------------------
__device__ __forceinline__ float2 cmul(float2 a, float2 b) {
    return make_float2(fmaf(a.x, b.x, -a.y * b.y), fmaf(a.x, b.y, a.y * b.x));
}
__device__ __forceinline__ float2 cadd(float2 a, float2 b) {
    return make_float2(a.x + b.x, a.y + b.y);
}
__device__ __forceinline__ float2 csub(float2 a, float2 b) {
    return make_float2(a.x - b.x, a.y - b.y);
}

__device__ __forceinline__ void dft4(float2 v[4]) {
    float2 t0 = cadd(v[0], v[2]);
    float2 t1 = csub(v[0], v[2]);
    float2 t2 = cadd(v[1], v[3]);
    float2 t3 = csub(v[1], v[3]);
    v[0] = cadd(t0, t2);
    v[2] = csub(t0, t2);
    v[1] = make_float2(t1.x + t3.y, t1.y - t3.x);
    v[3] = make_float2(t1.x - t3.y, t1.y + t3.x);
}

__device__ __forceinline__ void dft8(float2 v[8]) {
    float2 e[4] = { v[0], v[2], v[4], v[6] };
    float2 o[4] = { v[1], v[3], v[5], v[7] };
    dft4(e);
    dft4(o);
    const float s = 0.70710678118654752f;
    o[1] = make_float2(s * (o[1].x + o[1].y), s * (o[1].y - o[1].x));
    o[2] = make_float2(o[2].y, -o[2].x);
    o[3] = make_float2(s * (o[3].y - o[3].x), -s * (o[3].x + o[3].y));
#pragma unroll
    for (int k = 0; k < 4; k++) {
        v[k]     = cadd(e[k], o[k]);
        v[k + 4] = csub(e[k], o[k]);
    }
}

// ------------------------------ Stockham passes ----------------------------
template <int NS>
__device__ __forceinline__ void pass8(const float2* __restrict__ src,
                                      float2* __restrict__ dst, int j) {
    float2 v[8];
#pragma unroll
    for (int r = 0; r < 8; r++) v[r] = src[MAP(j + r * 256)];
    if (NS > 1) {
        int k0 = (j & (NS - 1)) * (256 / NS);
#pragma unroll
        for (int r = 1; r < 8; r++) v[r] = cmul(v[r], __ldg(&g_tw[k0 * r]));
    }
    dft8(v);
    int idxD = ((j & ~(NS - 1)) << 3) + (j & (NS - 1));
#pragma unroll
    for (int r = 0; r < 8; r++) dst[MAP(idxD + r * NS)] = v[r];
}

__device__ __forceinline__ void pass8_gmem(const float2* __restrict__ gsrc,
                                           float2* __restrict__ dst, int j) {
    float2 v[8];
#pragma unroll
    for (int r = 0; r < 8; r++) v[r] = gsrc[j + r * 256];
    dft8(v);
    int idxD = j << 3;
#pragma unroll
    for (int r = 0; r < 8; r++) dst[MAP(idxD + r)] = v[r];
}

__device__ __forceinline__ void pass4_512(const float2* __restrict__ src,
                                          float2* __restrict__ dst, int jj) {
    float2 v[4];
#pragma unroll
    for (int r = 0; r < 4; r++) v[r] = src[MAP(jj + r * 512)];
#pragma unroll
    for (int r = 1; r < 4; r++) v[r] = cmul(v[r], __ldg(&g_tw[jj * r]));
    dft4(v);
#pragma unroll
    for (int r = 0; r < 4; r++) dst[MAP(jj + r * 512)] = v[r];
}

__device__ __forceinline__ void pass4_512_out(const float2* __restrict__ src,
                                              float2* __restrict__ gdst, int jj) {
    float2 v[4];
#pragma unroll
    for (int r = 0; r < 4; r++) v[r] = src[MAP(jj + r * 512)];
#pragma unroll
    for (int r = 1; r < 4; r++) v[r] = cmul(v[r], __ldg(&g_tw[jj * r]));
    dft4(v);
    const float inv = 1.0f / 2048.0f;
#pragma unroll
    for (int r = 0; r < 4; r++)
        gdst[jj + r * 512] = make_float2(v[r].x * inv, -v[r].y * inv);
}

// bin index for thread t, slot i
__device__ __forceinline__ int slot_bin(int t, int i) {
    return (i < 4) ? (t + (i << 8)) : ((i < 8) ? (2048 - (t + ((i - 4) << 8))) : 1024);
}

// ------------------------------ main kernel --------------------------------
__global__ void __launch_bounds__(TPB, 6) fourier_block_kernel() {
    __shared__ float2   bufA[BUFSZ];
    __shared__ float2   bufB[BUFSZ];
    __shared__ unsigned maskbits[65];      // bit f set => keep bin f
    __shared__ unsigned s_bcnt;

    // histogram + boundary candidates alias bufB (dead between FFTs)
    unsigned* hist  = reinterpret_cast<unsigned*>(bufB);
    unsigned* candV = hist + NBINS;
    unsigned* candB = candV + CAP;

    const int tid  = threadIdx.x;
    const int lane = tid & 31;
    const int w    = tid >> 5;
    float2* series = reinterpret_cast<float2*>(g_scratch) + (size_t)blockIdx.x * NC;

    // dedicated smem zeroing at entry (ordered before use by the FFT syncs)
    if (tid < 65) maskbits[tid] = 0u;
    if (tid == 0) s_bcnt = 0u;

    // ---------------- forward FFT (gmem -> bufA) ----------------
    pass8_gmem(series, bufB, tid);
    __syncthreads();
    pass8<8>(bufB, bufA, tid);
    __syncthreads();
    pass8<64>(bufA, bufB, tid);
    __syncthreads();
    pass4_512(bufB, bufA, tid);
    pass4_512(bufB, bufA, tid + 256);
    __syncthreads();                                   // Z in bufA; bufB dead

    // zero hist (aliases bufB => only after the sync above)
#pragma unroll
    for (int q = 0; q < 4; q++) hist[tid + (q << 8)] = 0u;

    // ---------------- pairs pass 1: |X|^2 bits into registers ----------------
    unsigned fb[9];
#pragma unroll
    for (int q = 0; q < 4; q++) {
        int p = tid + (q << 8);                        // 0..1023
        float2 Zf = bufA[MAP(p)];
        float2 Zn = bufA[MAP((NC - p) & (NC - 1))];
        float2 S  = make_float2(Zf.x + Zn.x, Zf.y - Zn.y);
        float2 D  = make_float2(Zf.x - Zn.x, Zf.y + Zn.y);
        float2 H  = __ldg(&g_twh[p]);
        float2 T  = cmul(make_float2(-H.y, H.x), D);   // i*H*D
        float2 XA = make_float2(S.x - T.x, S.y - T.y); // 2*X[p]
        float2 XB = make_float2(S.x + T.x, S.y + T.y); // 2*conj(X[2048-p])
        fb[q]     = __float_as_uint(fmaf(XA.x, XA.x, XA.y * XA.y));
        fb[q + 4] = __float_as_uint(fmaf(XB.x, XB.x, XB.y * XB.y));
    }
    fb[8] = 0u;
    if (tid == 0) {                                    // bin 1024 (self-pair)
        float2 Zf = bufA[MAP(1024)];
        float2 S  = make_float2(2.0f * Zf.x, 0.0f);
        float2 D  = make_float2(0.0f, 2.0f * Zf.y);
        float2 H  = __ldg(&g_twh[1024]);
        float2 T  = cmul(make_float2(-H.y, H.x), D);
        float2 XA = make_float2(S.x - T.x, S.y - T.y);
        fb[8] = __float_as_uint(fmaf(XA.x, XA.x, XA.y * XA.y));
    }
    const int nv = (tid == 0) ? 9 : 8;
    __syncthreads();                                   // hist zero visible

    // ---------------- histogram of bit-prefixes ----------------
    for (int i = 0; i < nv; i++)
        atomicAdd(&hist[fb[i] >> 22], 1u);
    __syncthreads();

    // ------- threshold scan: every warp redundantly (no broadcast sync) -------
    unsigned T_, cgt;
    {
        int hi = (NBINS - 1) - lane * 32;              // lane0 covers top bins
        unsigned s = 0;
        for (int b2 = 0; b2 < 32; b2++) s += hist[hi - b2];
        unsigned cum = s;
#pragma unroll
        for (int o = 1; o < 32; o <<= 1) {
            unsigned t2 = __shfl_up_sync(0xffffffffu, cum, o);
            if (lane >= o) cum += t2;
        }
        unsigned excl = cum - s;                       // strictly-above count
        bool hit = (excl < 16u) && (excl + s >= 16u);
        unsigned hm = __ballot_sync(0xffffffffu, hit);
        int hl = __ffs(hm) - 1;
        unsigned tT = 0u, tc = 0u;
        if (lane == hl) {
            unsigned run = excl;
            int b = hi;
            while (run + hist[b] < 16u) { run += hist[b]; b--; }
            tT = (unsigned)b;
            tc = run;
        }
        T_  = __shfl_sync(0xffffffffu, tT, hl);
        cgt = __shfl_sync(0xffffffffu, tc, hl);
    }

    // ---------------- classify: definite keeps + boundary candidates ----------
    for (int i = 0; i < nv; i++) {
        unsigned pf = fb[i] >> 22;
        if (pf > T_) {
            int bn = slot_bin(tid, i);
            atomicOr(&maskbits[bn >> 5], 1u << (bn & 31));
        } else if (pf == T_) {
            unsigned s2 = atomicAdd(&s_bcnt, 1u);
            if (s2 < CAP) {
                candV[s2] = fb[i];
                candB[s2] = (unsigned)slot_bin(tid, i);
            }
        }
    }
    __syncthreads();

    // ---------------- warp0: pick remaining from boundary bin ----------------
    if (w == 0) {
        int need = 16 - (int)cgt;
        int m = (int)(s_bcnt < CAP ? s_bcnt : CAP);
        for (int it = 0; it < need; it++) {
            unsigned bv = 0u, bb = 0xFFFFFFFFu;
            for (int j = lane; j < m; j += 32) {
                unsigned v2 = candV[j], b2 = candB[j];
                if (v2 > bv || (v2 == bv && b2 < bb)) { bv = v2; bb = b2; }
            }
            unsigned best = redux_max_u32(bv);
            unsigned mb2 = (bv == best) ? bb : 0xFFFFFFFFu;
            unsigned wb = redux_min_u32(mb2);
            if (lane == 0) maskbits[wb >> 5] |= 1u << (wb & 31);
            for (int j = lane; j < m; j += 32)
                if (candB[j] == wb) candV[j] = 0u;
        }
    }
    __syncthreads();

    // ------- pairs pass 2: mask + inverse untangle, in place, no sync -------
#pragma unroll
    for (int q = 0; q < 5; q++) {
        int p = tid + (q << 8);
        if (q == 4 && tid != 0) break;
        if (q == 4) p = 1024;
        int binB = 2048 - p;
        unsigned ka = (maskbits[p >> 5] >> (p & 31)) & 1u;
        unsigned kb = (maskbits[binB >> 5] >> (binB & 31)) & 1u;
        if (!(ka | kb)) {                               // fast path: both dropped
            bufA[MAP(p)] = make_float2(0.0f, 0.0f);
            if (p != 0 && p != 1024)
                bufA[MAP(binB)] = make_float2(0.0f, 0.0f);
            continue;
        }
        int pm = (NC - p) & (NC - 1);
        float2 Zf = bufA[MAP(p)];
        float2 Zn = bufA[MAP(pm)];
        float2 S  = make_float2(Zf.x + Zn.x, Zf.y - Zn.y);
        float2 D  = make_float2(Zf.x - Zn.x, Zf.y + Zn.y);
        float2 H  = __ldg(&g_twh[p]);
        float2 T  = cmul(make_float2(-H.y, H.x), D);
        float2 A  = ka ? make_float2(0.5f * (S.x - T.x), 0.5f * (S.y - T.y))
                       : make_float2(0.0f, 0.0f);
        float2 Bc = kb ? make_float2(0.5f * (S.x + T.x), 0.5f * (S.y + T.y))
                       : make_float2(0.0f, 0.0f);       // conj(X'[2048-p])
        float2 St = make_float2(A.x + Bc.x, A.y + Bc.y);
        float2 Q  = make_float2(Bc.x - A.x, Bc.y - A.y);
        float2 Dt = cmul(make_float2(-H.y, -H.x), Q);   // -i*conj(H)*Q
        bufA[MAP(p)] = make_float2(0.5f * (St.x + Dt.x), -0.5f * (St.y + Dt.y));
        if (p != 0 && p != 1024)
            bufA[MAP(binB)] = make_float2(0.5f * (St.x - Dt.x), 0.5f * (St.y - Dt.y));
    }
    __syncthreads();

    // ---------------- inverse FFT via conj trick (bufA -> gmem) ----------------
    pass8<1>(bufA, bufB, tid);
    __syncthreads();
    pass8<8>(bufB, bufA, tid);
    __syncthreads();
    pass8<64>(bufA, bufB, tid);
    __syncthreads();
    pass4_512_out(bufB, series, tid);
    pass4_512_out(bufB, series, tid + 256);
}

// ------------------------------ twiddle init -------------------------------
// one value per thread, wide spread (65 blocks x 32), double sincospi
__global__ void twiddle_init_kernel() {
    int k = blockIdx.x * blockDim.x + threadIdx.x;
    if (k < NC) {
        double s, c;
        sincospi(-(double)k / 1024.0, &s, &c);   // angle -2*pi*k/2048
        g_tw[k] = make_float2((float)c, (float)s);
    }
    if (k < NF) {
        double s, c;
        sincospi((double)k / 2048.0, &s, &c);    // angle pi*k/2048
        g_twh[k] = make_float2((float)c, (float)(-s));
    }
}

// ------------------------------ transposes ---------------------------------
// fwd: x[b][l][c] -> scratch[b][c][l]; scratch side uses float4.
__global__ void __launch_bounds__(256) transpose_fwd_kernel(const float* __restrict__ x) {
    __shared__ float tile[32][129];
    const int b  = blockIdx.z;
    const int c0 = blockIdx.x * 32;
    const int l0 = blockIdx.y * 128;
    const float* xb = x + (size_t)b * LEN * CH;
    float* sb = g_scratch + (size_t)b * CH * LEN;
    const int lane = threadIdx.x & 31;
    const int wrp  = threadIdx.x >> 5;     // 0..7
#pragma unroll
    for (int k = 0; k < 16; k++) {
        int l = wrp + k * 8;
        tile[lane][l] = xb[(size_t)(l0 + l) * CH + (c0 + lane)];
    }
    __syncthreads();
#pragma unroll
    for (int m = 0; m < 4; m++) {
        int c = wrp * 4 + m;
        float4 v = make_float4(tile[c][4 * lane + 0], tile[c][4 * lane + 1],
                               tile[c][4 * lane + 2], tile[c][4 * lane + 3]);
        *reinterpret_cast<float4*>(&sb[(size_t)(c0 + c) * LEN + l0 + 4 * lane]) = v;
    }
}

// bwd: scratch[b][c][l] -> out[b][l][c]; scratch side uses float4.
__global__ void __launch_bounds__(256) transpose_bwd_kernel(float* __restrict__ out) {
    __shared__ float tile[32][129];
    const int b  = blockIdx.z;
    const int c0 = blockIdx.x * 32;
    const int l0 = blockIdx.y * 128;
    const float* sb = g_scratch + (size_t)b * CH * LEN;
    float* ob = out + (size_t)b * LEN * CH;
    const int lane = threadIdx.x & 31;
    const int wrp  = threadIdx.x >> 5;
#pragma unroll
    for (int m = 0; m < 4; m++) {
        int c = wrp * 4 + m;
        float4 v = *reinterpret_cast<const float4*>(
            &sb[(size_t)(c0 + c) * LEN + l0 + 4 * lane]);
        tile[c][4 * lane + 0] = v.x;
        tile[c][4 * lane + 1] = v.y;
        tile[c][4 * lane + 2] = v.z;
        tile[c][4 * lane + 3] = v.w;
    }
    __syncthreads();
#pragma unroll
    for (int k = 0; k < 16; k++) {
        int l = wrp + k * 8;
        ob[(size_t)(l0 + l) * CH + (c0 + lane)] = tile[lane][l];
    }
}

// ------------------------------ launch -------------------------------------
extern "C" void kernel_launch(void* const* d_in, const int* in_sizes, int n_in,
                              void* d_out, int out_size) {
    const float* x = (const float*)d_in[0];
    float* out = (float*)d_out;

    twiddle_init_kernel<<<65, 32>>>();
    transpose_fwd_kernel<<<dim3(CH / 32, LEN / 128, BATCH), 256>>>(x);
    fourier_block_kernel<<<BATCH * CH, TPB>>>();
    transpose_bwd_kernel<<<dim3(CH / 32, LEN / 128, BATCH), 256>>>(out);
}

// round 12
// speedup vs baseline: 1.7799x; 1.3238x over previous
#include <cuda_runtime.h>
#include <math.h>

// ---------------------------------------------------------------------------
// FourierBlock: rfft(L=4096) -> top-16 |X| per (b,c) -> mask -> irfft
// x: [B=64, L=4096, C=128] f32
//
// R6 structure exactly (best known: 335.9us), ONE delta: fast twiddle init.
//
//   k0: twiddle init (1 value/thread, sincospi, 65 blocks x 32 -> ~1us)
//   k1: transpose [B,L,C] -> scratch [B,C,L]   (float4 on scratch side)
//   k2: per-series kernel (1 CTA / series, 6 CTAs/SM):
//        packed real FFT (complex 2048, radix 8,8,8,4; 1st pass reads gmem)
//        pair-fused untangle -> |X|^2 bits in registers
//        1024-bin histogram top-16 (warp0 threshold + boundary refinement)
//        pair-fused mask + inverse untangle (bitmap, zero fast path)
//        inverse FFT (conj trick; last pass writes gmem with scale+conj)
//   k3: transpose scratch [B,C,L] -> out [B,L,C]
// ---------------------------------------------------------------------------

#define BATCH 64
#define LEN   4096
#define CH    128
#define NC    2048
#define NF    2049
#define TPB   256
#define NBINS 1024
#define CAP   1024

#define MAP(i) ((i) + ((i) >> 4))
#define BUFSZ  (MAP(2048) + 8)

__device__ __align__(16) float g_scratch[BATCH * CH * LEN];
__device__ float2 g_tw[NC];          // cis(-2*pi*k/2048)
__device__ float2 g_twh[NF];         // H[f] = cis(-pi*f/2048)

// ------------------------------ warp redux ---------------------------------
__device__ __forceinline__ unsigned redux_max_u32(unsigned v) {
    unsigned r;
    asm("redux.sync.max.u32 %0, %1, 0xffffffff;" : "=r"(r) : "r"(v));
    return r;
}
__device__ __forceinline__ unsigned redux_min_u32(unsigned v) {
    unsigned r;
    asm("redux.sync.min.u32 %0, %1, 0xffffffff;" : "=r"(r) : "r"(v));
    return r;
}

// ------------------------------ complex helpers ----------------------------
__device__ __forceinline__ float2 cmul(float2 a, float2 b) {
    return make_float2(fmaf(a.x, b.x, -a.y * b.y), fmaf(a.x, b.y, a.y * b.x));
}
__device__ __forceinline__ float2 cadd(float2 a, float2 b) {
    return make_float2(a.x + b.x, a.y + b.y);
}
__device__ __forceinline__ float2 csub(float2 a, float2 b) {
    return make_float2(a.x - b.x, a.y - b.y);
}

__device__ __forceinline__ void dft4(float2 v[4]) {
    float2 t0 = cadd(v[0], v[2]);
    float2 t1 = csub(v[0], v[2]);
    float2 t2 = cadd(v[1], v[3]);
    float2 t3 = csub(v[1], v[3]);
    v[0] = cadd(t0, t2);
    v[2] = csub(t0, t2);
    v[1] = make_float2(t1.x + t3.y, t1.y - t3.x);
    v[3] = make_float2(t1.x - t3.y, t1.y + t3.x);
}

__device__ __forceinline__ void dft8(float2 v[8]) {
    float2 e[4] = { v[0], v[2], v[4], v[6] };
    float2 o[4] = { v[1], v[3], v[5], v[7] };
    dft4(e);
    dft4(o);
    const float s = 0.70710678118654752f;
    o[1] = make_float2(s * (o[1].x + o[1].y), s * (o[1].y - o[1].x));
    o[2] = make_float2(o[2].y, -o[2].x);
    o[3] = make_float2(s * (o[3].y - o[3].x), -s * (o[3].x + o[3].y));
#pragma unroll
    for (int k = 0; k < 4; k++) {
        v[k]     = cadd(e[k], o[k]);
        v[k + 4] = csub(e[k], o[k]);
    }
}

// ------------------------------ Stockham passes ----------------------------
template <int NS>
__device__ __forceinline__ void pass8(const float2* __restrict__ src,
                                      float2* __restrict__ dst, int j) {
    float2 v[8];
#pragma unroll
    for (int r = 0; r < 8; r++) v[r] = src[MAP(j + r * 256)];
    if (NS > 1) {
        int k0 = (j & (NS - 1)) * (256 / NS);
#pragma unroll
        for (int r = 1; r < 8; r++) v[r] = cmul(v[r], __ldg(&g_tw[k0 * r]));
    }
    dft8(v);
    int idxD = ((j & ~(NS - 1)) << 3) + (j & (NS - 1));
#pragma unroll
    for (int r = 0; r < 8; r++) dst[MAP(idxD + r * NS)] = v[r];
}

__device__ __forceinline__ void pass8_gmem(const float2* __restrict__ gsrc,
                                           float2* __restrict__ dst, int j) {
    float2 v[8];
#pragma unroll
    for (int r = 0; r < 8; r++) v[r] = gsrc[j + r * 256];
    dft8(v);
    int idxD = j << 3;
#pragma unroll
    for (int r = 0; r < 8; r++) dst[MAP(idxD + r)] = v[r];
}

__device__ __forceinline__ void pass4_512(const float2* __restrict__ src,
                                          float2* __restrict__ dst, int jj) {
    float2 v[4];
#pragma unroll
    for (int r = 0; r < 4; r++) v[r] = src[MAP(jj + r * 512)];
#pragma unroll
    for (int r = 1; r < 4; r++) v[r] = cmul(v[r], __ldg(&g_tw[jj * r]));
    dft4(v);
#pragma unroll
    for (int r = 0; r < 4; r++) dst[MAP(jj + r * 512)] = v[r];
}

__device__ __forceinline__ void pass4_512_out(const float2* __restrict__ src,
                                              float2* __restrict__ gdst, int jj) {
    float2 v[4];
#pragma unroll
    for (int r = 0; r < 4; r++) v[r] = src[MAP(jj + r * 512)];
#pragma unroll
    for (int r = 1; r < 4; r++) v[r] = cmul(v[r], __ldg(&g_tw[jj * r]));
    dft4(v);
    const float inv = 1.0f / 2048.0f;
#pragma unroll
    for (int r = 0; r < 4; r++)
        gdst[jj + r * 512] = make_float2(v[r].x * inv, -v[r].y * inv);
}

// bin index for thread t, slot i
__device__ __forceinline__ int slot_bin(int t, int i) {
    return (i < 4) ? (t + (i << 8)) : ((i < 8) ? (2048 - (t + ((i - 4) << 8))) : 1024);
}

// ------------------------------ main kernel --------------------------------
__global__ void __launch_bounds__(TPB, 6) fourier_block_kernel() {
    __shared__ float2   bufA[BUFSZ];
    __shared__ float2   bufB[BUFSZ];
    __shared__ unsigned maskbits[65];      // bit f set => keep bin f
    __shared__ unsigned s_bcnt, s_T, s_cgt;

    // histogram + boundary candidates alias bufB (dead between FFTs)
    unsigned* hist  = reinterpret_cast<unsigned*>(bufB);
    unsigned* candV = hist + NBINS;
    unsigned* candB = candV + CAP;

    const int tid  = threadIdx.x;
    const int lane = tid & 31;
    const int w    = tid >> 5;
    float2* series = reinterpret_cast<float2*>(g_scratch) + (size_t)blockIdx.x * NC;

    // ---------------- forward FFT (gmem -> bufA) ----------------
    pass8_gmem(series, bufB, tid);
    __syncthreads();
    pass8<8>(bufB, bufA, tid);
    __syncthreads();
    pass8<64>(bufA, bufB, tid);
    __syncthreads();
    pass4_512(bufB, bufA, tid);
    pass4_512(bufB, bufA, tid + 256);
    __syncthreads();                                   // Z in bufA; bufB dead

    // zero hist / mask / counters (hist aliases bufB => after the sync above)
#pragma unroll
    for (int q = 0; q < 4; q++) hist[tid + (q << 8)] = 0u;
    if (tid < 65) maskbits[tid] = 0u;
    if (tid == 0) s_bcnt = 0u;

    // ---------------- pairs pass 1: |X|^2 bits into registers ----------------
    unsigned fb[9];
#pragma unroll
    for (int q = 0; q < 4; q++) {
        int p = tid + (q << 8);                        // 0..1023
        float2 Zf = bufA[MAP(p)];
        float2 Zn = bufA[MAP((NC - p) & (NC - 1))];
        float2 S  = make_float2(Zf.x + Zn.x, Zf.y - Zn.y);
        float2 D  = make_float2(Zf.x - Zn.x, Zf.y + Zn.y);
        float2 H  = __ldg(&g_twh[p]);
        float2 T  = cmul(make_float2(-H.y, H.x), D);   // i*H*D
        float2 XA = make_float2(S.x - T.x, S.y - T.y); // 2*X[p]
        float2 XB = make_float2(S.x + T.x, S.y + T.y); // 2*conj(X[2048-p])
        fb[q]     = __float_as_uint(fmaf(XA.x, XA.x, XA.y * XA.y));
        fb[q + 4] = __float_as_uint(fmaf(XB.x, XB.x, XB.y * XB.y));
    }
    fb[8] = 0u;
    if (tid == 0) {                                    // bin 1024 (self-pair)
        float2 Zf = bufA[MAP(1024)];
        float2 S  = make_float2(2.0f * Zf.x, 0.0f);
        float2 D  = make_float2(0.0f, 2.0f * Zf.y);
        float2 H  = __ldg(&g_twh[1024]);
        float2 T  = cmul(make_float2(-H.y, H.x), D);
        float2 XA = make_float2(S.x - T.x, S.y - T.y);
        fb[8] = __float_as_uint(fmaf(XA.x, XA.x, XA.y * XA.y));
    }
    const int nv = (tid == 0) ? 9 : 8;
    __syncthreads();                                   // hist zero visible

    // ---------------- histogram of bit-prefixes ----------------
    for (int i = 0; i < nv; i++)
        atomicAdd(&hist[fb[i] >> 22], 1u);
    __syncthreads();

    // ---------------- warp0: find threshold bin T, count above ----------------
    if (w == 0) {
        int hi = (NBINS - 1) - lane * 32;              // lane0 covers top bins
        unsigned s = 0;
        for (int b2 = 0; b2 < 32; b2++) s += hist[hi - b2];
        unsigned cum = s;
#pragma unroll
        for (int o = 1; o < 32; o <<= 1) {
            unsigned t2 = __shfl_up_sync(0xffffffffu, cum, o);
            if (lane >= o) cum += t2;
        }
        unsigned excl = cum - s;                       // strictly-above count
        bool hit = (excl < 16u) && (excl + s >= 16u);
        unsigned hm = __ballot_sync(0xffffffffu, hit);
        int hl = __ffs(hm) - 1;
        if (lane == hl) {
            unsigned run = excl;
            int b = hi;
            while (run + hist[b] < 16u) { run += hist[b]; b--; }
            s_T = (unsigned)b;
            s_cgt = run;
        }
    }
    __syncthreads();

    // ---------------- classify: definite keeps + boundary candidates ----------
    {
        unsigned T = s_T;
        for (int i = 0; i < nv; i++) {
            unsigned pf = fb[i] >> 22;
            if (pf > T) {
                int bn = slot_bin(tid, i);
                atomicOr(&maskbits[bn >> 5], 1u << (bn & 31));
            } else if (pf == T) {
                unsigned s2 = atomicAdd(&s_bcnt, 1u);
                if (s2 < CAP) {
                    candV[s2] = fb[i];
                    candB[s2] = (unsigned)slot_bin(tid, i);
                }
            }
        }
    }
    __syncthreads();

    // ---------------- warp0: pick remaining from boundary bin ----------------
    if (w == 0) {
        int need = 16 - (int)s_cgt;
        int m = (int)(s_bcnt < CAP ? s_bcnt : CAP);
        for (int it = 0; it < need; it++) {
            unsigned bv = 0u, bb = 0xFFFFFFFFu;
            for (int j = lane; j < m; j += 32) {
                unsigned v2 = candV[j], b2 = candB[j];
                if (v2 > bv || (v2 == bv && b2 < bb)) { bv = v2; bb = b2; }
            }
            unsigned best = redux_max_u32(bv);
            unsigned mb2 = (bv == best) ? bb : 0xFFFFFFFFu;
            unsigned wb = redux_min_u32(mb2);
            if (lane == 0) maskbits[wb >> 5] |= 1u << (wb & 31);
            for (int j = lane; j < m; j += 32)
                if (candB[j] == wb) candV[j] = 0u;
        }
    }
    __syncthreads();

    // ------- pairs pass 2: mask + inverse untangle, in place, no sync -------
#pragma unroll
    for (int q = 0; q < 5; q++) {
        int p = tid + (q << 8);
        if (q == 4 && tid != 0) break;
        if (q == 4) p = 1024;
        int binB = 2048 - p;
        unsigned ka = (maskbits[p >> 5] >> (p & 31)) & 1u;
        unsigned kb = (maskbits[binB >> 5] >> (binB & 31)) & 1u;
        if (!(ka | kb)) {                               // fast path: both dropped
            bufA[MAP(p)] = make_float2(0.0f, 0.0f);
            if (p != 0 && p != 1024)
                bufA[MAP(binB)] = make_float2(0.0f, 0.0f);
            continue;
        }
        int pm = (NC - p) & (NC - 1);
        float2 Zf = bufA[MAP(p)];
        float2 Zn = bufA[MAP(pm)];
        float2 S  = make_float2(Zf.x + Zn.x, Zf.y - Zn.y);
        float2 D  = make_float2(Zf.x - Zn.x, Zf.y + Zn.y);
        float2 H  = __ldg(&g_twh[p]);
        float2 T  = cmul(make_float2(-H.y, H.x), D);
        float2 A  = ka ? make_float2(0.5f * (S.x - T.x), 0.5f * (S.y - T.y))
                       : make_float2(0.0f, 0.0f);
        float2 Bc = kb ? make_float2(0.5f * (S.x + T.x), 0.5f * (S.y + T.y))
                       : make_float2(0.0f, 0.0f);       // conj(X'[2048-p])
        float2 St = make_float2(A.x + Bc.x, A.y + Bc.y);
        float2 Q  = make_float2(Bc.x - A.x, Bc.y - A.y);
        float2 Dt = cmul(make_float2(-H.y, -H.x), Q);   // -i*conj(H)*Q
        bufA[MAP(p)] = make_float2(0.5f * (St.x + Dt.x), -0.5f * (St.y + Dt.y));
        if (p != 0 && p != 1024)
            bufA[MAP(binB)] = make_float2(0.5f * (St.x - Dt.x), 0.5f * (St.y - Dt.y));
    }
    __syncthreads();

    // ---------------- inverse FFT via conj trick (bufA -> gmem) ----------------
    pass8<1>(bufA, bufB, tid);
    __syncthreads();
    pass8<8>(bufB, bufA, tid);
    __syncthreads();
    pass8<64>(bufA, bufB, tid);
    __syncthreads();
    pass4_512_out(bufB, series, tid);
    pass4_512_out(bufB, series, tid + 256);
}

// ------------------------------ twiddle init -------------------------------
// one value per thread, wide spread (65 blocks x 32), double sincospi
__global__ void twiddle_init_kernel() {
    int k = blockIdx.x * blockDim.x + threadIdx.x;
    if (k < NC) {
        double s, c;
        sincospi(-(double)k / 1024.0, &s, &c);   // angle -2*pi*k/2048
        g_tw[k] = make_float2((float)c, (float)s);
    }
    if (k < NF) {
        double s, c;
        sincospi((double)k / 2048.0, &s, &c);    // angle pi*k/2048
        g_twh[k] = make_float2((float)c, (float)(-s));
    }
}

// ------------------------------ transposes ---------------------------------
// fwd: x[b][l][c] -> scratch[b][c][l]; scratch side uses float4.
__global__ void __launch_bounds__(256) transpose_fwd_kernel(const float* __restrict__ x) {
    __shared__ float tile[32][129];
    const int b  = blockIdx.z;
    const int c0 = blockIdx.x * 32;
    const int l0 = blockIdx.y * 128;
    const float* xb = x + (size_t)b * LEN * CH;
    float* sb = g_scratch + (size_t)b * CH * LEN;
    const int lane = threadIdx.x & 31;
    const int wrp  = threadIdx.x >> 5;     // 0..7
#pragma unroll
    for (int k = 0; k < 16; k++) {
        int l = wrp + k * 8;
        tile[lane][l] = xb[(size_t)(l0 + l) * CH + (c0 + lane)];
    }
    __syncthreads();
#pragma unroll
    for (int m = 0; m < 4; m++) {
        int c = wrp * 4 + m;
        float4 v = make_float4(tile[c][4 * lane + 0], tile[c][4 * lane + 1],
                               tile[c][4 * lane + 2], tile[c][4 * lane + 3]);
        *reinterpret_cast<float4*>(&sb[(size_t)(c0 + c) * LEN + l0 + 4 * lane]) = v;
    }
}

// bwd: scratch[b][c][l] -> out[b][l][c]; scratch side uses float4.
__global__ void __launch_bounds__(256) transpose_bwd_kernel(float* __restrict__ out) {
    __shared__ float tile[32][129];
    const int b  = blockIdx.z;
    const int c0 = blockIdx.x * 32;
    const int l0 = blockIdx.y * 128;
    const float* sb = g_scratch + (size_t)b * CH * LEN;
    float* ob = out + (size_t)b * LEN * CH;
    const int lane = threadIdx.x & 31;
    const int wrp  = threadIdx.x >> 5;
#pragma unroll
    for (int m = 0; m < 4; m++) {
        int c = wrp * 4 + m;
        float4 v = *reinterpret_cast<const float4*>(
            &sb[(size_t)(c0 + c) * LEN + l0 + 4 * lane]);
        tile[c][4 * lane + 0] = v.x;
        tile[c][4 * lane + 1] = v.y;
        tile[c][4 * lane + 2] = v.z;
        tile[c][4 * lane + 3] = v.w;
    }
    __syncthreads();
#pragma unroll
    for (int k = 0; k < 16; k++) {
        int l = wrp + k * 8;
        ob[(size_t)(l0 + l) * CH + (c0 + lane)] = tile[lane][l];
    }
}

// ------------------------------ launch -------------------------------------
extern "C" void kernel_launch(void* const* d_in, const int* in_sizes, int n_in,
                              void* d_out, int out_size) {
    const float* x = (const float*)d_in[0];
    float* out = (float*)d_out;

    twiddle_init_kernel<<<65, 32>>>();
    transpose_fwd_kernel<<<dim3(CH / 32, LEN / 128, BATCH), 256>>>(x);
    fourier_block_kernel<<<BATCH * CH, TPB>>>();
    transpose_bwd_kernel<<<dim3(CH / 32, LEN / 128, BATCH), 256>>>(out);
}

// round 13
// speedup vs baseline: 1.7854x; 1.0031x over previous
#include <cuda_runtime.h>
#include <math.h>

// ---------------------------------------------------------------------------
// FourierBlock: rfft(L=4096) -> top-16 |X| per (b,c) -> mask -> irfft
// x: [B=64, L=4096, C=128] f32
//
// Base: R12 best (331.8us). Deltas:
//   (1) padded histogram -> conflict-free warp0 threshold scan
//   (2) definite-drop zeroing by warps 1-7 overlapped with warp0 refinement
//
//   k0: twiddle init (1 value/thread, sincospi, 65 blocks x 32)
//   k1: transpose [B,L,C] -> scratch [B,C,L]   (float4 on scratch side)
//   k2: per-series kernel (1 CTA / series, 6 CTAs/SM)
//   k3: transpose scratch [B,C,L] -> out [B,L,C]
// ---------------------------------------------------------------------------

#define BATCH 64
#define LEN   4096
#define CH    128
#define NC    2048
#define NF    2049
#define TPB   256
#define NBINS 1024
#define CAP   1024

#define MAP(i) ((i) + ((i) >> 4))
#define BUFSZ  (MAP(2048) + 8)
#define HMAP(b) ((b) + ((b) >> 5))     // padded histogram index (stride 33)
#define HSZ    (HMAP(NBINS - 1) + 2)   // 1056

__device__ __align__(16) float g_scratch[BATCH * CH * LEN];
__device__ float2 g_tw[NC];          // cis(-2*pi*k/2048)
__device__ float2 g_twh[NF];         // H[f] = cis(-pi*f/2048)

// ------------------------------ warp redux ---------------------------------
__device__ __forceinline__ unsigned redux_max_u32(unsigned v) {
    unsigned r;
    asm("redux.sync.max.u32 %0, %1, 0xffffffff;" : "=r"(r) : "r"(v));
    return r;
}
__device__ __forceinline__ unsigned redux_min_u32(unsigned v) {
    unsigned r;
    asm("redux.sync.min.u32 %0, %1, 0xffffffff;" : "=r"(r) : "r"(v));
    return r;
}

// ------------------------------ complex helpers ----------------------------
__device__ __forceinline__ float2 cmul(float2 a, float2 b) {
    return make_float2(fmaf(a.x, b.x, -a.y * b.y), fmaf(a.x, b.y, a.y * b.x));
}
__device__ __forceinline__ float2 cadd(float2 a, float2 b) {
    return make_float2(a.x + b.x, a.y + b.y);
}
__device__ __forceinline__ float2 csub(float2 a, float2 b) {
    return make_float2(a.x - b.x, a.y - b.y);
}

__device__ __forceinline__ void dft4(float2 v[4]) {
    float2 t0 = cadd(v[0], v[2]);
    float2 t1 = csub(v[0], v[2]);
    float2 t2 = cadd(v[1], v[3]);
    float2 t3 = csub(v[1], v[3]);
    v[0] = cadd(t0, t2);
    v[2] = csub(t0, t2);
    v[1] = make_float2(t1.x + t3.y, t1.y - t3.x);
    v[3] = make_float2(t1.x - t3.y, t1.y + t3.x);
}

__device__ __forceinline__ void dft8(float2 v[8]) {
    float2 e[4] = { v[0], v[2], v[4], v[6] };
    float2 o[4] = { v[1], v[3], v[5], v[7] };
    dft4(e);
    dft4(o);
    const float s = 0.70710678118654752f;
    o[1] = make_float2(s * (o[1].x + o[1].y), s * (o[1].y - o[1].x));
    o[2] = make_float2(o[2].y, -o[2].x);
    o[3] = make_float2(s * (o[3].y - o[3].x), -s * (o[3].x + o[3].y));
#pragma unroll
    for (int k = 0; k < 4; k++) {
        v[k]     = cadd(e[k], o[k]);
        v[k + 4] = csub(e[k], o[k]);
    }
}

// ------------------------------ Stockham passes ----------------------------
template <int NS>
__device__ __forceinline__ void pass8(const float2* __restrict__ src,
                                      float2* __restrict__ dst, int j) {
    float2 v[8];
#pragma unroll
    for (int r = 0; r < 8; r++) v[r] = src[MAP(j + r * 256)];
    if (NS > 1) {
        int k0 = (j & (NS - 1)) * (256 / NS);
#pragma unroll
        for (int r = 1; r < 8; r++) v[r] = cmul(v[r], __ldg(&g_tw[k0 * r]));
    }
    dft8(v);
    int idxD = ((j & ~(NS - 1)) << 3) + (j & (NS - 1));
#pragma unroll
    for (int r = 0; r < 8; r++) dst[MAP(idxD + r * NS)] = v[r];
}

__device__ __forceinline__ void pass8_gmem(const float2* __restrict__ gsrc,
                                           float2* __restrict__ dst, int j) {
    float2 v[8];
#pragma unroll
    for (int r = 0; r < 8; r++) v[r] = gsrc[j + r * 256];
    dft8(v);
    int idxD = j << 3;
#pragma unroll
    for (int r = 0; r < 8; r++) dst[MAP(idxD + r)] = v[r];
}

__device__ __forceinline__ void pass4_512(const float2* __restrict__ src,
                                          float2* __restrict__ dst, int jj) {
    float2 v[4];
#pragma unroll
    for (int r = 0; r < 4; r++) v[r] = src[MAP(jj + r * 512)];
#pragma unroll
    for (int r = 1; r < 4; r++) v[r] = cmul(v[r], __ldg(&g_tw[jj * r]));
    dft4(v);
#pragma unroll
    for (int r = 0; r < 4; r++) dst[MAP(jj + r * 512)] = v[r];
}

__device__ __forceinline__ void pass4_512_out(const float2* __restrict__ src,
                                              float2* __restrict__ gdst, int jj) {
    float2 v[4];
#pragma unroll
    for (int r = 0; r < 4; r++) v[r] = src[MAP(jj + r * 512)];
#pragma unroll
    for (int r = 1; r < 4; r++) v[r] = cmul(v[r], __ldg(&g_tw[jj * r]));
    dft4(v);
    const float inv = 1.0f / 2048.0f;
#pragma unroll
    for (int r = 0; r < 4; r++)
        gdst[jj + r * 512] = make_float2(v[r].x * inv, -v[r].y * inv);
}

// bin index for thread t, slot i
__device__ __forceinline__ int slot_bin(int t, int i) {
    return (i < 4) ? (t + (i << 8)) : ((i < 8) ? (2048 - (t + ((i - 4) << 8))) : 1024);
}

// ------------------------------ main kernel --------------------------------
__global__ void __launch_bounds__(TPB, 6) fourier_block_kernel() {
    __shared__ float2   bufA[BUFSZ];
    __shared__ float2   bufB[BUFSZ];
    __shared__ unsigned maskbits[65];      // bit f set => keep bin f
    __shared__ unsigned s_bcnt, s_T, s_cgt;

    // padded histogram + boundary candidates alias bufB (dead between FFTs)
    unsigned* hist  = reinterpret_cast<unsigned*>(bufB);
    unsigned* candV = hist + HSZ;
    unsigned* candB = candV + CAP;

    const int tid  = threadIdx.x;
    const int lane = tid & 31;
    const int w    = tid >> 5;
    float2* series = reinterpret_cast<float2*>(g_scratch) + (size_t)blockIdx.x * NC;

    // ---------------- forward FFT (gmem -> bufA) ----------------
    pass8_gmem(series, bufB, tid);
    __syncthreads();
    pass8<8>(bufB, bufA, tid);
    __syncthreads();
    pass8<64>(bufA, bufB, tid);
    __syncthreads();
    pass4_512(bufB, bufA, tid);
    pass4_512(bufB, bufA, tid + 256);
    __syncthreads();                                   // Z in bufA; bufB dead

    // zero hist / mask / counters (hist aliases bufB => after the sync above)
#pragma unroll
    for (int q = 0; q < 4; q++) hist[tid + (q << 8)] = 0u;
    if (tid < HSZ - 1024) hist[1024 + tid] = 0u;
    if (tid < 65) maskbits[tid] = 0u;
    if (tid == 0) s_bcnt = 0u;

    // ---------------- pairs pass 1: |X|^2 bits into registers ----------------
    unsigned fb[9];
#pragma unroll
    for (int q = 0; q < 4; q++) {
        int p = tid + (q << 8);                        // 0..1023
        float2 Zf = bufA[MAP(p)];
        float2 Zn = bufA[MAP((NC - p) & (NC - 1))];
        float2 S  = make_float2(Zf.x + Zn.x, Zf.y - Zn.y);
        float2 D  = make_float2(Zf.x - Zn.x, Zf.y + Zn.y);
        float2 H  = __ldg(&g_twh[p]);
        float2 T  = cmul(make_float2(-H.y, H.x), D);   // i*H*D
        float2 XA = make_float2(S.x - T.x, S.y - T.y); // 2*X[p]
        float2 XB = make_float2(S.x + T.x, S.y + T.y); // 2*conj(X[2048-p])
        fb[q]     = __float_as_uint(fmaf(XA.x, XA.x, XA.y * XA.y));
        fb[q + 4] = __float_as_uint(fmaf(XB.x, XB.x, XB.y * XB.y));
    }
    fb[8] = 0u;
    if (tid == 0) {                                    // bin 1024 (self-pair)
        float2 Zf = bufA[MAP(1024)];
        float2 S  = make_float2(2.0f * Zf.x, 0.0f);
        float2 D  = make_float2(0.0f, 2.0f * Zf.y);
        float2 H  = __ldg(&g_twh[1024]);
        float2 T  = cmul(make_float2(-H.y, H.x), D);
        float2 XA = make_float2(S.x - T.x, S.y - T.y);
        fb[8] = __float_as_uint(fmaf(XA.x, XA.x, XA.y * XA.y));
    }
    const int nv = (tid == 0) ? 9 : 8;
    __syncthreads();                                   // hist zero visible

    // ---------------- histogram of bit-prefixes (padded bins) ----------------
    for (int i = 0; i < nv; i++)
        atomicAdd(&hist[HMAP(fb[i] >> 22)], 1u);
    __syncthreads();

    // -------- warp0: threshold bin T + count above (conflict-free reads) ------
    if (w == 0) {
        int hi = (NBINS - 1) - lane * 32;              // lane0 covers top bins
        unsigned s = 0;
        for (int b2 = 0; b2 < 32; b2++) s += hist[HMAP(hi - b2)];
        unsigned cum = s;
#pragma unroll
        for (int o = 1; o < 32; o <<= 1) {
            unsigned t2 = __shfl_up_sync(0xffffffffu, cum, o);
            if (lane >= o) cum += t2;
        }
        unsigned excl = cum - s;                       // strictly-above count
        bool hit = (excl < 16u) && (excl + s >= 16u);
        unsigned hm = __ballot_sync(0xffffffffu, hit);
        int hl = __ffs(hm) - 1;
        if (lane == hl) {
            unsigned run = excl;
            int b = hi;
            while (run + hist[HMAP(b)] < 16u) { run += hist[HMAP(b)]; b--; }
            s_T = (unsigned)b;
            s_cgt = run;
        }
    }
    __syncthreads();
    const unsigned T_ = s_T;

    // ---------------- classify: definite keeps + boundary candidates ----------
    for (int i = 0; i < nv; i++) {
        unsigned pf = fb[i] >> 22;
        if (pf > T_) {
            int bn = slot_bin(tid, i);
            atomicOr(&maskbits[bn >> 5], 1u << (bn & 31));
        } else if (pf == T_) {
            unsigned s2 = atomicAdd(&s_bcnt, 1u);
            if (s2 < CAP) {
                candV[s2] = fb[i];
                candB[s2] = (unsigned)slot_bin(tid, i);
            }
        }
    }
    __syncthreads();

    // --- warp0: boundary refinement; warps 1-7: overlap definite-drop zeroing --
    unsigned dropmask = 0u;
    if (w == 0) {
        int need = 16 - (int)s_cgt;
        int m = (int)(s_bcnt < CAP ? s_bcnt : CAP);
        for (int it = 0; it < need; it++) {
            unsigned bv = 0u, bb = 0xFFFFFFFFu;
            for (int j = lane; j < m; j += 32) {
                unsigned v2 = candV[j], b2 = candB[j];
                if (v2 > bv || (v2 == bv && b2 < bb)) { bv = v2; bb = b2; }
            }
            unsigned best = redux_max_u32(bv);
            unsigned mb2 = (bv == best) ? bb : 0xFFFFFFFFu;
            unsigned wb = redux_min_u32(mb2);
            if (lane == 0) maskbits[wb >> 5] |= 1u << (wb & 31);
            for (int j = lane; j < m; j += 32)
                if (candB[j] == wb) candV[j] = 0u;
        }
    } else {
        // pairs with BOTH prefixes < T can never be kept: zero them now,
        // hidden under warp0's serial refinement. (bufA disjoint from
        // warp0's candV/maskbits working set.)
#pragma unroll
        for (int q = 0; q < 4; q++) {
            unsigned pfA = fb[q] >> 22;
            unsigned pfB = fb[q + 4] >> 22;
            if (pfA < T_ && pfB < T_) {
                int p = tid + (q << 8);
                bufA[MAP(p)] = make_float2(0.0f, 0.0f);
                bufA[MAP(2048 - p)] = make_float2(0.0f, 0.0f);
                dropmask |= 1u << q;
            }
        }
    }
    __syncthreads();

    // ------- pairs pass 2: mask + inverse untangle, in place, no sync -------
#pragma unroll
    for (int q = 0; q < 5; q++) {
        if (q < 4 && (dropmask >> q) & 1u) continue;    // already zeroed
        int p = tid + (q << 8);
        if (q == 4 && tid != 0) break;
        if (q == 4) p = 1024;
        int binB = 2048 - p;
        unsigned ka = (maskbits[p >> 5] >> (p & 31)) & 1u;
        unsigned kb = (maskbits[binB >> 5] >> (binB & 31)) & 1u;
        if (!(ka | kb)) {                               // fast path: both dropped
            bufA[MAP(p)] = make_float2(0.0f, 0.0f);
            if (p != 0 && p != 1024)
                bufA[MAP(binB)] = make_float2(0.0f, 0.0f);
            continue;
        }
        int pm = (NC - p) & (NC - 1);
        float2 Zf = bufA[MAP(p)];
        float2 Zn = bufA[MAP(pm)];
        float2 S  = make_float2(Zf.x + Zn.x, Zf.y - Zn.y);
        float2 D  = make_float2(Zf.x - Zn.x, Zf.y + Zn.y);
        float2 H  = __ldg(&g_twh[p]);
        float2 T  = cmul(make_float2(-H.y, H.x), D);
        float2 A  = ka ? make_float2(0.5f * (S.x - T.x), 0.5f * (S.y - T.y))
                       : make_float2(0.0f, 0.0f);
        float2 Bc = kb ? make_float2(0.5f * (S.x + T.x), 0.5f * (S.y + T.y))
                       : make_float2(0.0f, 0.0f);       // conj(X'[2048-p])
        float2 St = make_float2(A.x + Bc.x, A.y + Bc.y);
        float2 Q  = make_float2(Bc.x - A.x, Bc.y - A.y);
        float2 Dt = cmul(make_float2(-H.y, -H.x), Q);   // -i*conj(H)*Q
        bufA[MAP(p)] = make_float2(0.5f * (St.x + Dt.x), -0.5f * (St.y + Dt.y));
        if (p != 0 && p != 1024)
            bufA[MAP(binB)] = make_float2(0.5f * (St.x - Dt.x), 0.5f * (St.y - Dt.y));
    }
    __syncthreads();

    // ---------------- inverse FFT via conj trick (bufA -> gmem) ----------------
    pass8<1>(bufA, bufB, tid);
    __syncthreads();
    pass8<8>(bufB, bufA, tid);
    __syncthreads();
    pass8<64>(bufA, bufB, tid);
    __syncthreads();
    pass4_512_out(bufB, series, tid);
    pass4_512_out(bufB, series, tid + 256);
}

// ------------------------------ twiddle init -------------------------------
// one value per thread, wide spread (65 blocks x 32), double sincospi
__global__ void twiddle_init_kernel() {
    int k = blockIdx.x * blockDim.x + threadIdx.x;
    if (k < NC) {
        double s, c;
        sincospi(-(double)k / 1024.0, &s, &c);   // angle -2*pi*k/2048
        g_tw[k] = make_float2((float)c, (float)s);
    }
    if (k < NF) {
        double s, c;
        sincospi((double)k / 2048.0, &s, &c);    // angle pi*k/2048
        g_twh[k] = make_float2((float)c, (float)(-s));
    }
}

// ------------------------------ transposes ---------------------------------
// fwd: x[b][l][c] -> scratch[b][c][l]; scratch side uses float4.
__global__ void __launch_bounds__(256) transpose_fwd_kernel(const float* __restrict__ x) {
    __shared__ float tile[32][129];
    const int b  = blockIdx.z;
    const int c0 = blockIdx.x * 32;
    const int l0 = blockIdx.y * 128;
    const float* xb = x + (size_t)b * LEN * CH;
    float* sb = g_scratch + (size_t)b * CH * LEN;
    const int lane = threadIdx.x & 31;
    const int wrp  = threadIdx.x >> 5;     // 0..7
#pragma unroll
    for (int k = 0; k < 16; k++) {
        int l = wrp + k * 8;
        tile[lane][l] = xb[(size_t)(l0 + l) * CH + (c0 + lane)];
    }
    __syncthreads();
#pragma unroll
    for (int m = 0; m < 4; m++) {
        int c = wrp * 4 + m;
        float4 v = make_float4(tile[c][4 * lane + 0], tile[c][4 * lane + 1],
                               tile[c][4 * lane + 2], tile[c][4 * lane + 3]);
        *reinterpret_cast<float4*>(&sb[(size_t)(c0 + c) * LEN + l0 + 4 * lane]) = v;
    }
}

// bwd: scratch[b][c][l] -> out[b][l][c]; scratch side uses float4.
__global__ void __launch_bounds__(256) transpose_bwd_kernel(float* __restrict__ out) {
    __shared__ float tile[32][129];
    const int b  = blockIdx.z;
    const int c0 = blockIdx.x * 32;
    const int l0 = blockIdx.y * 128;
    const float* sb = g_scratch + (size_t)b * CH * LEN;
    float* ob = out + (size_t)b * LEN * CH;
    const int lane = threadIdx.x & 31;
    const int wrp  = threadIdx.x >> 5;
#pragma unroll
    for (int m = 0; m < 4; m++) {
        int c = wrp * 4 + m;
        float4 v = *reinterpret_cast<const float4*>(
            &sb[(size_t)(c0 + c) * LEN + l0 + 4 * lane]);
        tile[c][4 * lane + 0] = v.x;
        tile[c][4 * lane + 1] = v.y;
        tile[c][4 * lane + 2] = v.z;
        tile[c][4 * lane + 3] = v.w;
    }
    __syncthreads();
#pragma unroll
    for (int k = 0; k < 16; k++) {
        int l = wrp + k * 8;
        ob[(size_t)(l0 + l) * CH + (c0 + lane)] = tile[lane][l];
    }
}

// ------------------------------ launch -------------------------------------
extern "C" void kernel_launch(void* const* d_in, const int* in_sizes, int n_in,
                              void* d_out, int out_size) {
    const float* x = (const float*)d_in[0];
    float* out = (float*)d_out;

    twiddle_init_kernel<<<65, 32>>>();
    transpose_fwd_kernel<<<dim3(CH / 32, LEN / 128, BATCH), 256>>>(x);
    fourier_block_kernel<<<BATCH * CH, TPB>>>();
    transpose_bwd_kernel<<<dim3(CH / 32, LEN / 128, BATCH), 256>>>(out);
}